// round 1
// baseline (speedup 1.0000x reference)
#include <cuda_runtime.h>
#include <cuda_bf16.h>
#include <cstdint>
#include <math.h>

#define T_TOK 4096
#define DDIM  1024
#define HDIM  4096
#define NEXP  8

#define BM 128
#define BN 64
#define BK 32
#define NBM (T_TOK / BM)   // 32

// ---------------- device scratch (allocation-free rule: __device__ globals) ----------------
__device__ int   g_count[NEXP];
__device__ int   g_offset[NEXP];
__device__ int   g_tok[NEXP * T_TOK + 128];
__device__ float g_gw [NEXP * T_TOK + 128];
// compacted hidden activations: total assignments = 2*T_TOK, pad BM rows for clamped tail reads
__device__ float g_h[(size_t)(2 * T_TOK + BM) * HDIM];

// ---------------- helpers ----------------
__device__ __forceinline__ uint32_t smem_u32(const void* p) {
    return (uint32_t)__cvta_generic_to_shared(p);
}
__device__ __forceinline__ void ldsm_x4(uint32_t& r0, uint32_t& r1, uint32_t& r2, uint32_t& r3, uint32_t addr) {
    asm volatile("ldmatrix.sync.aligned.m8n8.x4.shared.b16 {%0,%1,%2,%3}, [%4];"
                 : "=r"(r0), "=r"(r1), "=r"(r2), "=r"(r3) : "r"(addr));
}
__device__ __forceinline__ void ldsm_x4_t(uint32_t& r0, uint32_t& r1, uint32_t& r2, uint32_t& r3, uint32_t addr) {
    asm volatile("ldmatrix.sync.aligned.m8n8.x4.trans.shared.b16 {%0,%1,%2,%3}, [%4];"
                 : "=r"(r0), "=r"(r1), "=r"(r2), "=r"(r3) : "r"(addr));
}
__device__ __forceinline__ void mma_bf16(float* c, const uint32_t* a, const uint32_t* b) {
    asm("mma.sync.aligned.m16n8k16.row.col.f32.bf16.bf16.f32 "
        "{%0,%1,%2,%3}, {%4,%5,%6,%7}, {%8,%9}, {%0,%1,%2,%3};"
        : "+f"(c[0]), "+f"(c[1]), "+f"(c[2]), "+f"(c[3])
        : "r"(a[0]), "r"(a[1]), "r"(a[2]), "r"(a[3]), "r"(b[0]), "r"(b[1]));
}
// split fp32 pair into bf16 hi + bf16 lo (Markidis decomposition), store packed to smem
__device__ __forceinline__ void split_store2(__nv_bfloat16* hp, __nv_bfloat16* lp, float a, float b) {
    __nv_bfloat16 h0 = __float2bfloat16(a);
    __nv_bfloat16 h1 = __float2bfloat16(b);
    float r0 = a - __bfloat162float(h0);
    float r1 = b - __bfloat162float(h1);
    __nv_bfloat162 hv; hv.x = h0; hv.y = h1;
    __nv_bfloat162 lv; lv.x = __float2bfloat16(r0); lv.y = __float2bfloat16(r1);
    *reinterpret_cast<__nv_bfloat162*>(hp) = hv;
    *reinterpret_cast<__nv_bfloat162*>(lp) = lv;
}

// ---------------- kernel 0: zero output + expert counters ----------------
__global__ void init_kernel(float* __restrict__ out) {
    int i = blockIdx.x * blockDim.x + threadIdx.x;
    if (i < T_TOK * DDIM) out[i] = 0.0f;
    if (i < NEXP) g_count[i] = 0;
}

// ---------------- kernel 1: router (warp per token) ----------------
__global__ void router_kernel(const float* __restrict__ x, const float* __restrict__ rw) {
    int warp = threadIdx.x >> 5, lane = threadIdx.x & 31;
    int t = blockIdx.x * 8 + warp;
    if (t >= T_TOK) return;
    const float* xr = x + (size_t)t * DDIM;
    float acc[NEXP];
#pragma unroll
    for (int e = 0; e < NEXP; e++) acc[e] = 0.f;
    for (int d = lane; d < DDIM; d += 32) {
        float xv = xr[d];
#pragma unroll
        for (int e = 0; e < NEXP; e++) acc[e] = fmaf(xv, rw[e * DDIM + d], acc[e]);
    }
#pragma unroll
    for (int e = 0; e < NEXP; e++) {
#pragma unroll
        for (int o = 16; o > 0; o >>= 1) acc[e] += __shfl_xor_sync(0xffffffffu, acc[e], o);
    }
    if (lane == 0) {
        float m = acc[0];
#pragma unroll
        for (int e = 1; e < NEXP; e++) m = fmaxf(m, acc[e]);
        float p[NEXP], s = 0.f;
#pragma unroll
        for (int e = 0; e < NEXP; e++) { p[e] = expf(acc[e] - m); s += p[e]; }
        float inv = 1.f / s;
        int i1 = 0; float v1 = p[0];
#pragma unroll
        for (int e = 1; e < NEXP; e++) if (p[e] > v1) { v1 = p[e]; i1 = e; }
        int i2 = (i1 == 0) ? 1 : 0; float v2 = p[i2];
#pragma unroll
        for (int e = 0; e < NEXP; e++) if (e != i1 && p[e] > v2) { v2 = p[e]; i2 = e; }
        v1 *= inv; v2 *= inv;                       // softmax probs of the top-2
        float dn = 1.f / (v1 + v2 + 1e-9f);         // renormalize (matches reference)
        int pos = atomicAdd(&g_count[i1], 1);
        g_tok[i1 * T_TOK + pos] = t; g_gw[i1 * T_TOK + pos] = v1 * dn;
        pos = atomicAdd(&g_count[i2], 1);
        g_tok[i2 * T_TOK + pos] = t; g_gw[i2 * T_TOK + pos] = v2 * dn;
    }
}

// ---------------- kernel 2: exclusive prefix over 8 counts ----------------
__global__ void offsets_kernel() {
    if (threadIdx.x == 0) {
        int o = 0;
#pragma unroll
        for (int e = 0; e < NEXP; e++) { g_offset[e] = o; o += g_count[e]; }
    }
}

// ---------------- kernel 3: fc1 grouped GEMM (gathered x @ w1[e]) + GELU ----------------
__global__ void __launch_bounds__(256) fc1_kernel(const float* __restrict__ x,
                                                  const float* __restrict__ w1) {
    __shared__ __align__(16) __nv_bfloat16 As_hi[BM][BK + 8];
    __shared__ __align__(16) __nv_bfloat16 As_lo[BM][BK + 8];
    __shared__ __align__(16) __nv_bfloat16 Bs_hi[BK][BN + 8];
    __shared__ __align__(16) __nv_bfloat16 Bs_lo[BK][BN + 8];
    __shared__ int s_tok[BM];

    int e    = blockIdx.x / NBM;
    int bm   = blockIdx.x % NBM;
    int n_e  = g_count[e];
    int row0 = bm * BM;
    if (row0 >= n_e) return;
    int goff = g_offset[e];

    int tid = threadIdx.x;
    if (tid < BM) s_tok[tid] = g_tok[e * T_TOK + row0 + tid];  // tail reads stale-but-in-range tokens

    int nb = blockIdx.y * BN;
    const float* Bsrc = w1 + (size_t)e * DDIM * HDIM + nb;

    int warp = tid >> 5, lane = tid & 31;
    int wm = (warp & 3) * 32;
    int wn = (warp >> 2) * 32;
    int grp = lane >> 3, lr = lane & 7;
    int gq = lane >> 2, tg = lane & 3;

    float c[2][4][4];
#pragma unroll
    for (int a = 0; a < 2; a++)
#pragma unroll
        for (int b = 0; b < 4; b++)
#pragma unroll
            for (int i = 0; i < 4; i++) c[a][b][i] = 0.f;

    __syncthreads();  // s_tok visible

    for (int k0 = 0; k0 < DDIM; k0 += BK) {
        // A tile: 128x32 fp32, gathered rows, split to bf16 hi/lo
#pragma unroll
        for (int it = 0; it < 4; it++) {
            int q = it * 256 + tid;
            int row = q >> 3, c4 = (q & 7) * 4;
            float4 v = *reinterpret_cast<const float4*>(x + (size_t)s_tok[row] * DDIM + k0 + c4);
            split_store2(&As_hi[row][c4],     &As_lo[row][c4],     v.x, v.y);
            split_store2(&As_hi[row][c4 + 2], &As_lo[row][c4 + 2], v.z, v.w);
        }
        // B tile: 32x64 fp32 from w1[e] (K-major rows, N contiguous)
#pragma unroll
        for (int it = 0; it < 2; it++) {
            int q = it * 256 + tid;
            int row = q >> 4, c4 = (q & 15) * 4;
            float4 v = *reinterpret_cast<const float4*>(Bsrc + (size_t)(k0 + row) * HDIM + c4);
            split_store2(&Bs_hi[row][c4],     &Bs_lo[row][c4],     v.x, v.y);
            split_store2(&Bs_hi[row][c4 + 2], &Bs_lo[row][c4 + 2], v.z, v.w);
        }
        __syncthreads();
#pragma unroll
        for (int kk = 0; kk < 2; kk++) {
            uint32_t ah[2][4], al[2][4], bh[4][2], bl[4][2];
#pragma unroll
            for (int mt = 0; mt < 2; mt++) {
                int row = wm + mt * 16 + (grp & 1) * 8 + lr;
                int kof = kk * 16 + (grp >> 1) * 8;
                ldsm_x4(ah[mt][0], ah[mt][1], ah[mt][2], ah[mt][3], smem_u32(&As_hi[row][kof]));
                ldsm_x4(al[mt][0], al[mt][1], al[mt][2], al[mt][3], smem_u32(&As_lo[row][kof]));
            }
#pragma unroll
            for (int j = 0; j < 2; j++) {
                int krow = kk * 16 + (grp & 1) * 8 + lr;
                int ncol = wn + j * 16 + (grp >> 1) * 8;
                ldsm_x4_t(bh[j*2][0], bh[j*2][1], bh[j*2+1][0], bh[j*2+1][1], smem_u32(&Bs_hi[krow][ncol]));
                ldsm_x4_t(bl[j*2][0], bl[j*2][1], bl[j*2+1][0], bl[j*2+1][1], smem_u32(&Bs_lo[krow][ncol]));
            }
#pragma unroll
            for (int mt = 0; mt < 2; mt++)
#pragma unroll
                for (int nt = 0; nt < 4; nt++) {
                    mma_bf16(c[mt][nt], ah[mt], bh[nt]);
                    mma_bf16(c[mt][nt], ah[mt], bl[nt]);
                    mma_bf16(c[mt][nt], al[mt], bh[nt]);
                }
        }
        __syncthreads();
    }

    int rows_valid = n_e - row0;
#pragma unroll
    for (int mt = 0; mt < 2; mt++)
#pragma unroll
        for (int nt = 0; nt < 4; nt++)
#pragma unroll
            for (int i = 0; i < 4; i++) {
                int r   = wm + mt * 16 + gq + (i >> 1) * 8;
                int col = nb + wn + nt * 8 + tg * 2 + (i & 1);
                if (r < rows_valid) {
                    float v = c[mt][nt][i];
                    v = 0.5f * v * (1.0f + erff(v * 0.70710678118654752f));  // exact GELU
                    g_h[(size_t)(goff + row0 + r) * HDIM + col] = v;
                }
            }
}

// ---------------- kernel 4: fc2 grouped GEMM (g_h @ w2[e]) + weighted scatter-add ----------------
__global__ void __launch_bounds__(256) fc2_kernel(const float* __restrict__ w2,
                                                  float* __restrict__ out) {
    __shared__ __align__(16) __nv_bfloat16 As_hi[BM][BK + 8];
    __shared__ __align__(16) __nv_bfloat16 As_lo[BM][BK + 8];
    __shared__ __align__(16) __nv_bfloat16 Bs_hi[BK][BN + 8];
    __shared__ __align__(16) __nv_bfloat16 Bs_lo[BK][BN + 8];
    __shared__ int   s_tok[BM];
    __shared__ float s_w[BM];

    int e    = blockIdx.x / NBM;
    int bm   = blockIdx.x % NBM;
    int n_e  = g_count[e];
    int row0 = bm * BM;
    if (row0 >= n_e) return;
    int goff = g_offset[e];

    int tid = threadIdx.x;
    if (tid < BM) {
        s_tok[tid] = g_tok[e * T_TOK + row0 + tid];
        s_w[tid]   = g_gw [e * T_TOK + row0 + tid];
    }

    int nb = blockIdx.y * BN;
    const float* Bsrc = w2 + (size_t)e * HDIM * DDIM + nb;
    const float* Asrc = g_h + (size_t)(goff + row0) * HDIM;

    int warp = tid >> 5, lane = tid & 31;
    int wm = (warp & 3) * 32;
    int wn = (warp >> 2) * 32;
    int grp = lane >> 3, lr = lane & 7;
    int gq = lane >> 2, tg = lane & 3;

    float c[2][4][4];
#pragma unroll
    for (int a = 0; a < 2; a++)
#pragma unroll
        for (int b = 0; b < 4; b++)
#pragma unroll
            for (int i = 0; i < 4; i++) c[a][b][i] = 0.f;

    __syncthreads();

    for (int k0 = 0; k0 < HDIM; k0 += BK) {
#pragma unroll
        for (int it = 0; it < 4; it++) {
            int q = it * 256 + tid;
            int row = q >> 3, c4 = (q & 7) * 4;
            float4 v = *reinterpret_cast<const float4*>(Asrc + (size_t)row * HDIM + k0 + c4);
            split_store2(&As_hi[row][c4],     &As_lo[row][c4],     v.x, v.y);
            split_store2(&As_hi[row][c4 + 2], &As_lo[row][c4 + 2], v.z, v.w);
        }
#pragma unroll
        for (int it = 0; it < 2; it++) {
            int q = it * 256 + tid;
            int row = q >> 4, c4 = (q & 15) * 4;
            float4 v = *reinterpret_cast<const float4*>(Bsrc + (size_t)(k0 + row) * DDIM + c4);
            split_store2(&Bs_hi[row][c4],     &Bs_lo[row][c4],     v.x, v.y);
            split_store2(&Bs_hi[row][c4 + 2], &Bs_lo[row][c4 + 2], v.z, v.w);
        }
        __syncthreads();
#pragma unroll
        for (int kk = 0; kk < 2; kk++) {
            uint32_t ah[2][4], al[2][4], bh[4][2], bl[4][2];
#pragma unroll
            for (int mt = 0; mt < 2; mt++) {
                int row = wm + mt * 16 + (grp & 1) * 8 + lr;
                int kof = kk * 16 + (grp >> 1) * 8;
                ldsm_x4(ah[mt][0], ah[mt][1], ah[mt][2], ah[mt][3], smem_u32(&As_hi[row][kof]));
                ldsm_x4(al[mt][0], al[mt][1], al[mt][2], al[mt][3], smem_u32(&As_lo[row][kof]));
            }
#pragma unroll
            for (int j = 0; j < 2; j++) {
                int krow = kk * 16 + (grp & 1) * 8 + lr;
                int ncol = wn + j * 16 + (grp >> 1) * 8;
                ldsm_x4_t(bh[j*2][0], bh[j*2][1], bh[j*2+1][0], bh[j*2+1][1], smem_u32(&Bs_hi[krow][ncol]));
                ldsm_x4_t(bl[j*2][0], bl[j*2][1], bl[j*2+1][0], bl[j*2+1][1], smem_u32(&Bs_lo[krow][ncol]));
            }
#pragma unroll
            for (int mt = 0; mt < 2; mt++)
#pragma unroll
                for (int nt = 0; nt < 4; nt++) {
                    mma_bf16(c[mt][nt], ah[mt], bh[nt]);
                    mma_bf16(c[mt][nt], ah[mt], bl[nt]);
                    mma_bf16(c[mt][nt], al[mt], bh[nt]);
                }
        }
        __syncthreads();
    }

    int rows_valid = n_e - row0;
#pragma unroll
    for (int mt = 0; mt < 2; mt++)
#pragma unroll
        for (int nt = 0; nt < 4; nt++)
#pragma unroll
            for (int i = 0; i < 4; i++) {
                int r   = wm + mt * 16 + gq + (i >> 1) * 8;
                int col = nb + wn + nt * 8 + tg * 2 + (i & 1);
                if (r < rows_valid) {
                    atomicAdd(&out[(size_t)s_tok[r] * DDIM + col], c[mt][nt][i] * s_w[r]);
                }
            }
}

// ---------------- launch ----------------
extern "C" void kernel_launch(void* const* d_in, const int* in_sizes, int n_in,
                              void* d_out, int out_size) {
    (void)in_sizes; (void)n_in; (void)out_size;
    const float* x  = (const float*)d_in[0];
    const float* rw = (const float*)d_in[1];
    const float* w1 = (const float*)d_in[2];
    const float* w2 = (const float*)d_in[3];
    float* out = (float*)d_out;

    init_kernel<<<(T_TOK * DDIM + 255) / 256, 256>>>(out);
    router_kernel<<<T_TOK / 8, 256>>>(x, rw);
    offsets_kernel<<<1, 32>>>();
    dim3 g1(NEXP * NBM, HDIM / BN);   // 256 x 64
    fc1_kernel<<<g1, 256>>>(x, w1);
    dim3 g2(NEXP * NBM, DDIM / BN);   // 256 x 16
    fc2_kernel<<<g2, 256>>>(w2, out);
}

// round 3
// speedup vs baseline: 2.2591x; 2.2591x over previous
#include <cuda_runtime.h>
#include <cuda_fp16.h>
#include <cstdint>
#include <math.h>

#define T_TOK 4096
#define DDIM  1024
#define HDIM  4096
#define NEXP  8

#define BM 128
#define BN 64
#define BK 64
#define NBM (T_TOK / BM)   // 32

// ---------------- device scratch ----------------
__device__ int   g_count[NEXP];
__device__ int   g_offset[NEXP];
__device__ int   g_tok[NEXP * T_TOK];
__device__ float g_gw [NEXP * T_TOK];
// pre-split activations (fp16 hi/lo pair == ~21-bit exact)
__device__ __half g_xh[(size_t)T_TOK * DDIM];
__device__ __half g_xl[(size_t)T_TOK * DDIM];
// weights as single fp16 (error source, ~2.8e-4 RMS per GEMM)
__device__ __half g_w1h[(size_t)NEXP * DDIM * HDIM];   // [E][D][H]
__device__ __half g_w2h[(size_t)NEXP * HDIM * DDIM];   // [E][H][D]
// compacted hidden activations, pre-split fp16 hi/lo
__device__ __half g_hh[(size_t)(2 * T_TOK + BM) * HDIM];
__device__ __half g_hl[(size_t)(2 * T_TOK + BM) * HDIM];

// ---------------- smem layout ----------------
#define SM_TOK  0        // 128 int
#define SM_W    512      // 128 float
#define SM_DATA 1024
#define STG     40960    // per stage: A_hi 16K | A_lo 16K | B 8K
#define A_HI    0
#define A_LO    16384
#define B_OFF   32768
#define SMEM_TOTAL (SM_DATA + 2 * STG)   // 82944 B -> 2 CTAs/SM

// ---------------- helpers ----------------
__device__ __forceinline__ uint32_t smem_u32(const void* p) {
    return (uint32_t)__cvta_generic_to_shared(p);
}
__device__ __forceinline__ void ldsm_x4(uint32_t& r0, uint32_t& r1, uint32_t& r2, uint32_t& r3, uint32_t addr) {
    asm volatile("ldmatrix.sync.aligned.m8n8.x4.shared.b16 {%0,%1,%2,%3}, [%4];"
                 : "=r"(r0), "=r"(r1), "=r"(r2), "=r"(r3) : "r"(addr));
}
__device__ __forceinline__ void ldsm_x4_t(uint32_t& r0, uint32_t& r1, uint32_t& r2, uint32_t& r3, uint32_t addr) {
    asm volatile("ldmatrix.sync.aligned.m8n8.x4.trans.shared.b16 {%0,%1,%2,%3}, [%4];"
                 : "=r"(r0), "=r"(r1), "=r"(r2), "=r"(r3) : "r"(addr));
}
__device__ __forceinline__ void mma_f16(float* c, const uint32_t* a, const uint32_t* b) {
    asm("mma.sync.aligned.m16n8k16.row.col.f32.f16.f16.f32 "
        "{%0,%1,%2,%3}, {%4,%5,%6,%7}, {%8,%9}, {%0,%1,%2,%3};"
        : "+f"(c[0]), "+f"(c[1]), "+f"(c[2]), "+f"(c[3])
        : "r"(a[0]), "r"(a[1]), "r"(a[2]), "r"(a[3]), "r"(b[0]), "r"(b[1]));
}
__device__ __forceinline__ void cp16(uint32_t dst, const void* src) {
    asm volatile("cp.async.cg.shared.global [%0], [%1], 16;" :: "r"(dst), "l"(src));
}
__device__ __forceinline__ void cp_commit() { asm volatile("cp.async.commit_group;"); }

__device__ __forceinline__ void split2h(__half2* hp, __half2* lp, float a, float b) {
    __half ha = __float2half_rn(a), hb = __float2half_rn(b);
    __half2 hv; hv.x = ha; hv.y = hb;
    __half2 lv;
    lv.x = __float2half_rn(a - __half2float(ha));
    lv.y = __float2half_rn(b - __half2float(hb));
    *hp = hv; *lp = lv;
}
__device__ __forceinline__ float gelu_f(float v) {
    return 0.5f * v * (1.0f + erff(v * 0.7071067811865476f));
}
__device__ __forceinline__ uint32_t swz(uint32_t off) { return off ^ ((off >> 3) & 0x70); }

// ---------------- kernel 0: zero output + counters ----------------
__global__ void init_kernel(float* __restrict__ out) {
    int i = blockIdx.x * blockDim.x + threadIdx.x;
    if (i < T_TOK * DDIM) out[i] = 0.0f;
    if (i < NEXP) g_count[i] = 0;
}

// ---------------- prep: fp32 -> fp16 hi/lo split (activations) ----------------
__global__ void split_x_kernel(const float* __restrict__ in) {
    size_t i = (size_t)blockIdx.x * blockDim.x + threadIdx.x;   // float4 index
    float4 v = reinterpret_cast<const float4*>(in)[i];
    __half2 h0, l0, h1, l1;
    split2h(&h0, &l0, v.x, v.y);
    split2h(&h1, &l1, v.z, v.w);
    reinterpret_cast<__half2*>(g_xh)[2 * i]     = h0;
    reinterpret_cast<__half2*>(g_xh)[2 * i + 1] = h1;
    reinterpret_cast<__half2*>(g_xl)[2 * i]     = l0;
    reinterpret_cast<__half2*>(g_xl)[2 * i + 1] = l1;
}

// ---------------- prep: fp32 -> single fp16 (weights) ----------------
__global__ void split_w_kernel(const float* __restrict__ in, __half* __restrict__ out) {
    size_t i = (size_t)blockIdx.x * blockDim.x + threadIdx.x;   // float4 index
    float4 v = reinterpret_cast<const float4*>(in)[i];
    __half2 p0; p0.x = __float2half_rn(v.x); p0.y = __float2half_rn(v.y);
    __half2 p1; p1.x = __float2half_rn(v.z); p1.y = __float2half_rn(v.w);
    reinterpret_cast<__half2*>(out)[2 * i]     = p0;
    reinterpret_cast<__half2*>(out)[2 * i + 1] = p1;
}

// ---------------- router (warp per token, fp32) ----------------
__global__ void router_kernel(const float* __restrict__ x, const float* __restrict__ rw) {
    int warp = threadIdx.x >> 5, lane = threadIdx.x & 31;
    int t = blockIdx.x * 8 + warp;
    if (t >= T_TOK) return;
    const float* xr = x + (size_t)t * DDIM;
    float acc[NEXP];
#pragma unroll
    for (int e = 0; e < NEXP; e++) acc[e] = 0.f;
    for (int d = lane; d < DDIM; d += 32) {
        float xv = xr[d];
#pragma unroll
        for (int e = 0; e < NEXP; e++) acc[e] = fmaf(xv, rw[e * DDIM + d], acc[e]);
    }
#pragma unroll
    for (int e = 0; e < NEXP; e++)
#pragma unroll
        for (int o = 16; o > 0; o >>= 1) acc[e] += __shfl_xor_sync(0xffffffffu, acc[e], o);
    if (lane == 0) {
        float m = acc[0];
#pragma unroll
        for (int e = 1; e < NEXP; e++) m = fmaxf(m, acc[e]);
        float p[NEXP], s = 0.f;
#pragma unroll
        for (int e = 0; e < NEXP; e++) { p[e] = expf(acc[e] - m); s += p[e]; }
        float inv = 1.f / s;
        int i1 = 0; float v1 = p[0];
#pragma unroll
        for (int e = 1; e < NEXP; e++) if (p[e] > v1) { v1 = p[e]; i1 = e; }
        int i2 = (i1 == 0) ? 1 : 0; float v2 = p[i2];
#pragma unroll
        for (int e = 0; e < NEXP; e++) if (e != i1 && p[e] > v2) { v2 = p[e]; i2 = e; }
        v1 *= inv; v2 *= inv;
        float dn = 1.f / (v1 + v2 + 1e-9f);
        int pos = atomicAdd(&g_count[i1], 1);
        g_tok[i1 * T_TOK + pos] = t; g_gw[i1 * T_TOK + pos] = v1 * dn;
        pos = atomicAdd(&g_count[i2], 1);
        g_tok[i2 * T_TOK + pos] = t; g_gw[i2 * T_TOK + pos] = v2 * dn;
    }
}

__global__ void offsets_kernel() {
    if (threadIdx.x == 0) {
        int o = 0;
#pragma unroll
        for (int e = 0; e < NEXP; e++) { g_offset[e] = o; o += g_count[e]; }
    }
}

// ---------------- fc1: grouped GEMM (gathered x @ w1) + GELU, fp16 2-term ----------------
__global__ void __launch_bounds__(256, 2) fc1_kernel() {
    extern __shared__ __align__(128) char smem[];
    const uint32_t smb = smem_u32(smem);
    int tid = threadIdx.x, warp = tid >> 5, lane = tid & 31;
    int e = blockIdx.x / NBM, bm = blockIdx.x % NBM;
    int n_e = g_count[e], row0 = bm * BM;
    if (row0 >= n_e) return;
    int goff = g_offset[e];
    int nb = blockIdx.y * BN;

    int* s_tok = (int*)(smem + SM_TOK);
    if (tid < BM) s_tok[tid] = g_tok[e * T_TOK + row0 + tid];
    __syncthreads();

    const __half* bsrc = g_w1h + (size_t)e * DDIM * HDIM + nb;

    auto load_chunk = [&](int k0, int st) {
        uint32_t ub = smb + SM_DATA + st * STG;
#pragma unroll
        for (int it = 0; it < 4; it++) {          // A: 128 rows x 8 chunks (hi+lo)
            int idx = it * 256 + tid;
            int row = idx >> 3, p = idx & 7;
            size_t so = (size_t)s_tok[row] * DDIM + k0 + p * 8;
            uint32_t d = row * 128 + swz(p * 16 + ((row & 7) << 4) * 0) ; // placeholder
            d = row * 128 + ((p ^ (row & 7)) << 4);
            cp16(ub + A_HI + d, g_xh + so);
            cp16(ub + A_LO + d, g_xl + so);
        }
#pragma unroll
        for (int it = 0; it < 2; it++) {          // B: 64 k-rows x 8 chunks
            int idx = it * 256 + tid;
            int row = idx >> 3, p = idx & 7;
            uint32_t d = row * 128 + ((p ^ (row & 7)) << 4);
            cp16(ub + B_OFF + d, bsrc + (size_t)(k0 + row) * HDIM + p * 8);
        }
        cp_commit();
    };

    int wm = (warp & 3) * 32;
    int wn = (warp >> 2) * 32;
    int grp = lane >> 3, lr = lane & 7;

    float c[2][4][4];
#pragma unroll
    for (int a = 0; a < 2; a++)
#pragma unroll
        for (int b = 0; b < 4; b++)
#pragma unroll
            for (int i = 0; i < 4; i++) c[a][b][i] = 0.f;

    load_chunk(0, 0);

    const int NCH = DDIM / BK;   // 16
    for (int i = 0; i < NCH; i++) {
        int st = i & 1;
        if (i + 1 < NCH) {
            load_chunk((i + 1) * BK, st ^ 1);
            asm volatile("cp.async.wait_group 1;" ::: "memory");
        } else {
            asm volatile("cp.async.wait_group 0;" ::: "memory");
        }
        __syncthreads();
        uint32_t ab_h = smb + SM_DATA + st * STG + A_HI;
        uint32_t ab_l = smb + SM_DATA + st * STG + A_LO;
        uint32_t bb   = smb + SM_DATA + st * STG + B_OFF;
#pragma unroll
        for (int kk = 0; kk < 4; kk++) {
            uint32_t ah[2][4], al[2][4], bh[4][2];
#pragma unroll
            for (int mt = 0; mt < 2; mt++) {
                int row = wm + mt * 16 + (grp & 1) * 8 + lr;
                int kof = kk * 16 + (grp >> 1) * 8;
                uint32_t sw = swz(row * 128 + kof * 2);
                ldsm_x4(ah[mt][0], ah[mt][1], ah[mt][2], ah[mt][3], ab_h + sw);
                ldsm_x4(al[mt][0], al[mt][1], al[mt][2], al[mt][3], ab_l + sw);
            }
#pragma unroll
            for (int j = 0; j < 2; j++) {
                int krow = kk * 16 + (grp & 1) * 8 + lr;
                int ncol = wn + j * 16 + (grp >> 1) * 8;
                uint32_t sw = swz(krow * 128 + ncol * 2);
                ldsm_x4_t(bh[j*2][0], bh[j*2][1], bh[j*2+1][0], bh[j*2+1][1], bb + sw);
            }
#pragma unroll
            for (int mt = 0; mt < 2; mt++)
#pragma unroll
                for (int nt = 0; nt < 4; nt++) {
                    mma_f16(c[mt][nt], ah[mt], bh[nt]);
                    mma_f16(c[mt][nt], al[mt], bh[nt]);
                }
        }
        __syncthreads();
    }

    // epilogue: GELU, fp16 hi/lo split, store compacted hidden
    int rows_valid = n_e - row0;
    int gq = lane >> 2, tg = lane & 3;
#pragma unroll
    for (int mt = 0; mt < 2; mt++)
#pragma unroll
        for (int nt = 0; nt < 4; nt++) {
            int col = nb + wn + nt * 8 + tg * 2;
            int r0r = wm + mt * 16 + gq;
            if (r0r < rows_valid) {
                size_t o = (size_t)(goff + row0 + r0r) * HDIM + col;
                split2h((__half2*)(g_hh + o), (__half2*)(g_hl + o),
                        gelu_f(c[mt][nt][0]), gelu_f(c[mt][nt][1]));
            }
            int r1r = r0r + 8;
            if (r1r < rows_valid) {
                size_t o = (size_t)(goff + row0 + r1r) * HDIM + col;
                split2h((__half2*)(g_hh + o), (__half2*)(g_hl + o),
                        gelu_f(c[mt][nt][2]), gelu_f(c[mt][nt][3]));
            }
        }
}

// ---------------- fc2: grouped GEMM (hidden @ w2) + weighted scatter-add ----------------
__global__ void __launch_bounds__(256, 2) fc2_kernel(float* __restrict__ out) {
    extern __shared__ __align__(128) char smem[];
    const uint32_t smb = smem_u32(smem);
    int tid = threadIdx.x, warp = tid >> 5, lane = tid & 31;
    int e = blockIdx.x / NBM, bm = blockIdx.x % NBM;
    int n_e = g_count[e], row0 = bm * BM;
    if (row0 >= n_e) return;
    int goff = g_offset[e];
    int nb = blockIdx.y * BN;

    int* s_tok = (int*)(smem + SM_TOK);
    float* s_w = (float*)(smem + SM_W);
    if (tid < BM) {
        s_tok[tid] = g_tok[e * T_TOK + row0 + tid];
        s_w[tid]   = g_gw [e * T_TOK + row0 + tid];
    }
    __syncthreads();

    const __half* ah_src = g_hh + (size_t)(goff + row0) * HDIM;
    const __half* al_src = g_hl + (size_t)(goff + row0) * HDIM;
    const __half* bsrc   = g_w2h + (size_t)e * HDIM * DDIM + nb;

    auto load_chunk = [&](int k0, int st) {
        uint32_t ub = smb + SM_DATA + st * STG;
#pragma unroll
        for (int it = 0; it < 4; it++) {
            int idx = it * 256 + tid;
            int row = idx >> 3, p = idx & 7;
            size_t so = (size_t)row * HDIM + k0 + p * 8;
            uint32_t d = row * 128 + ((p ^ (row & 7)) << 4);
            cp16(ub + A_HI + d, ah_src + so);
            cp16(ub + A_LO + d, al_src + so);
        }
#pragma unroll
        for (int it = 0; it < 2; it++) {
            int idx = it * 256 + tid;
            int row = idx >> 3, p = idx & 7;
            uint32_t d = row * 128 + ((p ^ (row & 7)) << 4);
            cp16(ub + B_OFF + d, bsrc + (size_t)(k0 + row) * DDIM + p * 8);
        }
        cp_commit();
    };

    int wm = (warp & 3) * 32;
    int wn = (warp >> 2) * 32;
    int grp = lane >> 3, lr = lane & 7;

    float c[2][4][4];
#pragma unroll
    for (int a = 0; a < 2; a++)
#pragma unroll
        for (int b = 0; b < 4; b++)
#pragma unroll
            for (int i = 0; i < 4; i++) c[a][b][i] = 0.f;

    load_chunk(0, 0);

    const int NCH = HDIM / BK;   // 64
    for (int i = 0; i < NCH; i++) {
        int st = i & 1;
        if (i + 1 < NCH) {
            load_chunk((i + 1) * BK, st ^ 1);
            asm volatile("cp.async.wait_group 1;" ::: "memory");
        } else {
            asm volatile("cp.async.wait_group 0;" ::: "memory");
        }
        __syncthreads();
        uint32_t ab_h = smb + SM_DATA + st * STG + A_HI;
        uint32_t ab_l = smb + SM_DATA + st * STG + A_LO;
        uint32_t bb   = smb + SM_DATA + st * STG + B_OFF;
#pragma unroll
        for (int kk = 0; kk < 4; kk++) {
            uint32_t ah[2][4], al[2][4], bh[4][2];
#pragma unroll
            for (int mt = 0; mt < 2; mt++) {
                int row = wm + mt * 16 + (grp & 1) * 8 + lr;
                int kof = kk * 16 + (grp >> 1) * 8;
                uint32_t sw = swz(row * 128 + kof * 2);
                ldsm_x4(ah[mt][0], ah[mt][1], ah[mt][2], ah[mt][3], ab_h + sw);
                ldsm_x4(al[mt][0], al[mt][1], al[mt][2], al[mt][3], ab_l + sw);
            }
#pragma unroll
            for (int j = 0; j < 2; j++) {
                int krow = kk * 16 + (grp & 1) * 8 + lr;
                int ncol = wn + j * 16 + (grp >> 1) * 8;
                uint32_t sw = swz(krow * 128 + ncol * 2);
                ldsm_x4_t(bh[j*2][0], bh[j*2][1], bh[j*2+1][0], bh[j*2+1][1], bb + sw);
            }
#pragma unroll
            for (int mt = 0; mt < 2; mt++)
#pragma unroll
                for (int nt = 0; nt < 4; nt++) {
                    mma_f16(c[mt][nt], ah[mt], bh[nt]);
                    mma_f16(c[mt][nt], al[mt], bh[nt]);
                }
        }
        __syncthreads();
    }

    int rows_valid = n_e - row0;
    int gq = lane >> 2, tg = lane & 3;
#pragma unroll
    for (int mt = 0; mt < 2; mt++)
#pragma unroll
        for (int nt = 0; nt < 4; nt++) {
            int col = nb + wn + nt * 8 + tg * 2;
#pragma unroll
            for (int half = 0; half < 2; half++) {
                int r = wm + mt * 16 + gq + half * 8;
                if (r < rows_valid) {
                    float gw = s_w[r];
                    float* orow = out + (size_t)s_tok[r] * DDIM + col;
                    atomicAdd(orow,     c[mt][nt][half * 2]     * gw);
                    atomicAdd(orow + 1, c[mt][nt][half * 2 + 1] * gw);
                }
            }
        }
}

// ---------------- launch ----------------
extern "C" void kernel_launch(void* const* d_in, const int* in_sizes, int n_in,
                              void* d_out, int out_size) {
    (void)in_sizes; (void)n_in; (void)out_size;
    const float* x  = (const float*)d_in[0];
    const float* rw = (const float*)d_in[1];
    const float* w1 = (const float*)d_in[2];
    const float* w2 = (const float*)d_in[3];
    float* out = (float*)d_out;

    cudaFuncSetAttribute(fc1_kernel, cudaFuncAttributeMaxDynamicSharedMemorySize, SMEM_TOTAL);
    cudaFuncSetAttribute(fc2_kernel, cudaFuncAttributeMaxDynamicSharedMemorySize, SMEM_TOTAL);

    init_kernel<<<(T_TOK * DDIM + 255) / 256, 256>>>(out);

    __half *w1h, *w2h;
    cudaGetSymbolAddress((void**)&w1h, g_w1h);
    cudaGetSymbolAddress((void**)&w2h, g_w2h);
    split_x_kernel<<<(T_TOK * DDIM / 4) / 256, 256>>>(x);
    split_w_kernel<<<((size_t)NEXP * DDIM * HDIM / 4) / 256, 256>>>(w1, w1h);
    split_w_kernel<<<((size_t)NEXP * HDIM * DDIM / 4) / 256, 256>>>(w2, w2h);

    router_kernel<<<T_TOK / 8, 256>>>(x, rw);
    offsets_kernel<<<1, 32>>>();

    dim3 g1(NEXP * NBM, HDIM / BN);   // 256 x 64
    fc1_kernel<<<g1, 256, SMEM_TOTAL>>>();
    dim3 g2(NEXP * NBM, DDIM / BN);   // 256 x 16
    fc2_kernel<<<g2, 256, SMEM_TOTAL>>>(out);
}

// round 4
// speedup vs baseline: 3.9346x; 1.7417x over previous
#include <cuda_runtime.h>
#include <cuda_fp16.h>
#include <cstdint>
#include <math.h>

#define T_TOK 4096
#define DDIM  1024
#define HDIM  4096
#define NEXP  8

#define BM 128
#define BN 128
#define BK 64
#define NBM (T_TOK / BM)   // 32

// ---------------- device scratch ----------------
__device__ int   g_count[NEXP];
__device__ int   g_offset[NEXP];
__device__ int   g_tok[NEXP * T_TOK];
__device__ float g_gw [NEXP * T_TOK];
__device__ __half g_xh[(size_t)T_TOK * DDIM];                  // x as fp16
__device__ __half g_w1h[(size_t)NEXP * DDIM * HDIM];           // [E][D][H] fp16
__device__ __half g_w2h[(size_t)NEXP * HDIM * DDIM];           // [E][H][D] fp16
__device__ __half g_hh[(size_t)(2 * T_TOK + BM) * HDIM];       // hidden fp16 (compacted)

// ---------------- smem layout ----------------
#define SM_TOK  0        // 128 int
#define SM_W    512      // 128 float
#define SM_DATA 1024
#define A_OFF   0        // 128 x 64 fp16 = 16384 B (128 B/row, 8 chunks)
#define B_OFF   16384    //  64 x 128 fp16 = 16384 B (256 B/row, 16 chunks)
#define STG     32768
#define SMEM_TOTAL (SM_DATA + 2 * STG)   // 66560 B

// ---------------- helpers ----------------
__device__ __forceinline__ uint32_t smem_u32(const void* p) {
    return (uint32_t)__cvta_generic_to_shared(p);
}
__device__ __forceinline__ void ldsm_x4(uint32_t& r0, uint32_t& r1, uint32_t& r2, uint32_t& r3, uint32_t addr) {
    asm volatile("ldmatrix.sync.aligned.m8n8.x4.shared.b16 {%0,%1,%2,%3}, [%4];"
                 : "=r"(r0), "=r"(r1), "=r"(r2), "=r"(r3) : "r"(addr));
}
__device__ __forceinline__ void ldsm_x4_t(uint32_t& r0, uint32_t& r1, uint32_t& r2, uint32_t& r3, uint32_t addr) {
    asm volatile("ldmatrix.sync.aligned.m8n8.x4.trans.shared.b16 {%0,%1,%2,%3}, [%4];"
                 : "=r"(r0), "=r"(r1), "=r"(r2), "=r"(r3) : "r"(addr));
}
__device__ __forceinline__ void mma_f16(float* c, const uint32_t* a, const uint32_t* b) {
    asm("mma.sync.aligned.m16n8k16.row.col.f32.f16.f16.f32 "
        "{%0,%1,%2,%3}, {%4,%5,%6,%7}, {%8,%9}, {%0,%1,%2,%3};"
        : "+f"(c[0]), "+f"(c[1]), "+f"(c[2]), "+f"(c[3])
        : "r"(a[0]), "r"(a[1]), "r"(a[2]), "r"(a[3]), "r"(b[0]), "r"(b[1]));
}
__device__ __forceinline__ void cp16(uint32_t dst, const void* src) {
    asm volatile("cp.async.cg.shared.global [%0], [%1], 16;" :: "r"(dst), "l"(src));
}
__device__ __forceinline__ void cp_commit() { asm volatile("cp.async.commit_group;"); }

__device__ __forceinline__ float gelu_f(float v) {
    return 0.5f * v * (1.0f + erff(v * 0.7071067811865476f));
}
// A tile: 128 B/row (8x16B chunks), chunk p swizzled by row
__device__ __forceinline__ uint32_t a_addr(uint32_t row, uint32_t p) {
    return row * 128 + ((p ^ (row & 7)) << 4);
}
// B tile: 256 B/row (16x16B chunks), low-3 chunk bits swizzled by row
__device__ __forceinline__ uint32_t b_addr(uint32_t row, uint32_t p) {
    return row * 256 + (((p & 8) | ((p ^ row) & 7)) << 4);
}

// ---------------- kernel 0: zero output + counters ----------------
__global__ void init_kernel(float* __restrict__ out) {
    int i = blockIdx.x * blockDim.x + threadIdx.x;
    if (i < T_TOK * DDIM) out[i] = 0.0f;
    if (i < NEXP) g_count[i] = 0;
}

// ---------------- prep: fp32 -> fp16 ----------------
__global__ void tohalf_kernel(const float* __restrict__ in, __half* __restrict__ out) {
    size_t i = (size_t)blockIdx.x * blockDim.x + threadIdx.x;   // float4 index
    float4 v = reinterpret_cast<const float4*>(in)[i];
    __half2 p0; p0.x = __float2half_rn(v.x); p0.y = __float2half_rn(v.y);
    __half2 p1; p1.x = __float2half_rn(v.z); p1.y = __float2half_rn(v.w);
    reinterpret_cast<__half2*>(out)[2 * i]     = p0;
    reinterpret_cast<__half2*>(out)[2 * i + 1] = p1;
}

// ---------------- router (warp per token, fp32) ----------------
__global__ void router_kernel(const float* __restrict__ x, const float* __restrict__ rw) {
    int warp = threadIdx.x >> 5, lane = threadIdx.x & 31;
    int t = blockIdx.x * 8 + warp;
    if (t >= T_TOK) return;
    const float* xr = x + (size_t)t * DDIM;
    float acc[NEXP];
#pragma unroll
    for (int e = 0; e < NEXP; e++) acc[e] = 0.f;
    for (int d = lane; d < DDIM; d += 32) {
        float xv = xr[d];
#pragma unroll
        for (int e = 0; e < NEXP; e++) acc[e] = fmaf(xv, rw[e * DDIM + d], acc[e]);
    }
#pragma unroll
    for (int e = 0; e < NEXP; e++)
#pragma unroll
        for (int o = 16; o > 0; o >>= 1) acc[e] += __shfl_xor_sync(0xffffffffu, acc[e], o);
    if (lane == 0) {
        float m = acc[0];
#pragma unroll
        for (int e = 1; e < NEXP; e++) m = fmaxf(m, acc[e]);
        float p[NEXP], s = 0.f;
#pragma unroll
        for (int e = 0; e < NEXP; e++) { p[e] = expf(acc[e] - m); s += p[e]; }
        float inv = 1.f / s;
        int i1 = 0; float v1 = p[0];
#pragma unroll
        for (int e = 1; e < NEXP; e++) if (p[e] > v1) { v1 = p[e]; i1 = e; }
        int i2 = (i1 == 0) ? 1 : 0; float v2 = p[i2];
#pragma unroll
        for (int e = 0; e < NEXP; e++) if (e != i1 && p[e] > v2) { v2 = p[e]; i2 = e; }
        v1 *= inv; v2 *= inv;
        float dn = 1.f / (v1 + v2 + 1e-9f);
        int pos = atomicAdd(&g_count[i1], 1);
        g_tok[i1 * T_TOK + pos] = t; g_gw[i1 * T_TOK + pos] = v1 * dn;
        pos = atomicAdd(&g_count[i2], 1);
        g_tok[i2 * T_TOK + pos] = t; g_gw[i2 * T_TOK + pos] = v2 * dn;
    }
}

__global__ void offsets_kernel() {
    if (threadIdx.x == 0) {
        int o = 0;
#pragma unroll
        for (int e = 0; e < NEXP; e++) { g_offset[e] = o; o += g_count[e]; }
    }
}

// ================= shared GEMM core (BM=128, BN=128, BK=64, 8 warps) =================
// A rows from a_row_ptr(row) (fp16, K-major); B rows from bsrc + k*ldb (fp16, N-major).
// Accumulators c[2][8][4]; warp tile 32x64.

// ---------------- fc1: grouped GEMM (gathered x @ w1) + GELU ----------------
__global__ void __launch_bounds__(256, 2) fc1_kernel() {
    extern __shared__ __align__(128) char smem[];
    const uint32_t smb = smem_u32(smem);
    int tid = threadIdx.x, warp = tid >> 5, lane = tid & 31;
    int e = blockIdx.x / NBM, bm = blockIdx.x % NBM;
    int n_e = g_count[e], row0 = bm * BM;
    if (row0 >= n_e) return;
    int goff = g_offset[e];
    int nb = blockIdx.y * BN;

    int* s_tok = (int*)(smem + SM_TOK);
    if (tid < BM) s_tok[tid] = g_tok[e * T_TOK + row0 + tid];
    __syncthreads();

    const __half* bsrc = g_w1h + (size_t)e * DDIM * HDIM + nb;

    auto load_chunk = [&](int k0, int st) {
        uint32_t ub = smb + SM_DATA + st * STG;
#pragma unroll
        for (int it = 0; it < 4; it++) {          // A: 128 rows x 8 chunks
            int idx = it * 256 + tid;
            int row = idx >> 3, p = idx & 7;
            cp16(ub + A_OFF + a_addr(row, p), g_xh + (size_t)s_tok[row] * DDIM + k0 + p * 8);
        }
#pragma unroll
        for (int it = 0; it < 4; it++) {          // B: 64 k-rows x 16 chunks
            int idx = it * 256 + tid;
            int row = idx >> 4, p = idx & 15;
            cp16(ub + B_OFF + b_addr(row, p), bsrc + (size_t)(k0 + row) * HDIM + p * 8);
        }
        cp_commit();
    };

    int wm = (warp & 3) * 32;
    int wn = (warp >> 2) * 64;
    int grp = lane >> 3, lr = lane & 7;

    float c[2][8][4];
#pragma unroll
    for (int a = 0; a < 2; a++)
#pragma unroll
        for (int b = 0; b < 8; b++)
#pragma unroll
            for (int i = 0; i < 4; i++) c[a][b][i] = 0.f;

    load_chunk(0, 0);

    const int NCH = DDIM / BK;   // 16
    for (int i = 0; i < NCH; i++) {
        int st = i & 1;
        if (i + 1 < NCH) {
            load_chunk((i + 1) * BK, st ^ 1);
            asm volatile("cp.async.wait_group 1;" ::: "memory");
        } else {
            asm volatile("cp.async.wait_group 0;" ::: "memory");
        }
        __syncthreads();
        uint32_t ab = smb + SM_DATA + st * STG + A_OFF;
        uint32_t bb = smb + SM_DATA + st * STG + B_OFF;
#pragma unroll
        for (int kk = 0; kk < 4; kk++) {
            uint32_t af[2][4], bf[8][2];
#pragma unroll
            for (int mt = 0; mt < 2; mt++) {
                int row = wm + mt * 16 + (grp & 1) * 8 + lr;
                int kof = kk * 16 + (grp >> 1) * 8;
                ldsm_x4(af[mt][0], af[mt][1], af[mt][2], af[mt][3],
                        ab + a_addr(row, 0) + ((kof * 2) ^ ((row & 7) << 4)) - ((0 ^ (row & 7)) << 4));
            }
#pragma unroll
            for (int j = 0; j < 4; j++) {
                int krow = kk * 16 + (grp & 1) * 8 + lr;
                int ncol = wn + j * 16 + (grp >> 1) * 8;
                uint32_t p = (uint32_t)ncol >> 3;
                uint32_t ba = krow * 256 + (((p & 8) | ((p ^ (uint32_t)krow) & 7)) << 4);
                ldsm_x4_t(bf[j*2][0], bf[j*2][1], bf[j*2+1][0], bf[j*2+1][1], bb + ba);
            }
#pragma unroll
            for (int mt = 0; mt < 2; mt++)
#pragma unroll
                for (int nt = 0; nt < 8; nt++)
                    mma_f16(c[mt][nt], af[mt], bf[nt]);
        }
        __syncthreads();
    }

    // epilogue: GELU -> fp16 hidden (compacted)
    int rows_valid = n_e - row0;
    int gq = lane >> 2, tg = lane & 3;
#pragma unroll
    for (int mt = 0; mt < 2; mt++)
#pragma unroll
        for (int nt = 0; nt < 8; nt++) {
            int col = nb + wn + nt * 8 + tg * 2;
#pragma unroll
            for (int half = 0; half < 2; half++) {
                int r = wm + mt * 16 + gq + half * 8;
                if (r < rows_valid) {
                    __half2 hv;
                    hv.x = __float2half_rn(gelu_f(c[mt][nt][half * 2]));
                    hv.y = __float2half_rn(gelu_f(c[mt][nt][half * 2 + 1]));
                    *reinterpret_cast<__half2*>(g_hh + (size_t)(goff + row0 + r) * HDIM + col) = hv;
                }
            }
        }
}

// ---------------- fc2: grouped GEMM (hidden @ w2) + weighted scatter-add ----------------
__global__ void __launch_bounds__(256, 2) fc2_kernel(float* __restrict__ out) {
    extern __shared__ __align__(128) char smem[];
    const uint32_t smb = smem_u32(smem);
    int tid = threadIdx.x, warp = tid >> 5, lane = tid & 31;
    int e = blockIdx.x / NBM, bm = blockIdx.x % NBM;
    int n_e = g_count[e], row0 = bm * BM;
    if (row0 >= n_e) return;
    int goff = g_offset[e];
    int nb = blockIdx.y * BN;

    int* s_tok = (int*)(smem + SM_TOK);
    float* s_w = (float*)(smem + SM_W);
    if (tid < BM) {
        s_tok[tid] = g_tok[e * T_TOK + row0 + tid];
        s_w[tid]   = g_gw [e * T_TOK + row0 + tid];
    }
    __syncthreads();

    const __half* asrc = g_hh + (size_t)(goff + row0) * HDIM;
    const __half* bsrc = g_w2h + (size_t)e * HDIM * DDIM + nb;

    auto load_chunk = [&](int k0, int st) {
        uint32_t ub = smb + SM_DATA + st * STG;
#pragma unroll
        for (int it = 0; it < 4; it++) {
            int idx = it * 256 + tid;
            int row = idx >> 3, p = idx & 7;
            cp16(ub + A_OFF + a_addr(row, p), asrc + (size_t)row * HDIM + k0 + p * 8);
        }
#pragma unroll
        for (int it = 0; it < 4; it++) {
            int idx = it * 256 + tid;
            int row = idx >> 4, p = idx & 15;
            cp16(ub + B_OFF + b_addr(row, p), bsrc + (size_t)(k0 + row) * DDIM + p * 8);
        }
        cp_commit();
    };

    int wm = (warp & 3) * 32;
    int wn = (warp >> 2) * 64;
    int grp = lane >> 3, lr = lane & 7;

    float c[2][8][4];
#pragma unroll
    for (int a = 0; a < 2; a++)
#pragma unroll
        for (int b = 0; b < 8; b++)
#pragma unroll
            for (int i = 0; i < 4; i++) c[a][b][i] = 0.f;

    load_chunk(0, 0);

    const int NCH = HDIM / BK;   // 64
    for (int i = 0; i < NCH; i++) {
        int st = i & 1;
        if (i + 1 < NCH) {
            load_chunk((i + 1) * BK, st ^ 1);
            asm volatile("cp.async.wait_group 1;" ::: "memory");
        } else {
            asm volatile("cp.async.wait_group 0;" ::: "memory");
        }
        __syncthreads();
        uint32_t ab = smb + SM_DATA + st * STG + A_OFF;
        uint32_t bb = smb + SM_DATA + st * STG + B_OFF;
#pragma unroll
        for (int kk = 0; kk < 4; kk++) {
            uint32_t af[2][4], bf[8][2];
#pragma unroll
            for (int mt = 0; mt < 2; mt++) {
                int row = wm + mt * 16 + (grp & 1) * 8 + lr;
                int kof = kk * 16 + (grp >> 1) * 8;
                uint32_t p = (uint32_t)(kof * 2) >> 4;
                ldsm_x4(af[mt][0], af[mt][1], af[mt][2], af[mt][3],
                        ab + row * 128 + ((p ^ ((uint32_t)row & 7)) << 4));
            }
#pragma unroll
            for (int j = 0; j < 4; j++) {
                int krow = kk * 16 + (grp & 1) * 8 + lr;
                int ncol = wn + j * 16 + (grp >> 1) * 8;
                uint32_t p = (uint32_t)ncol >> 3;
                uint32_t ba = krow * 256 + (((p & 8) | ((p ^ (uint32_t)krow) & 7)) << 4);
                ldsm_x4_t(bf[j*2][0], bf[j*2][1], bf[j*2+1][0], bf[j*2+1][1], bb + ba);
            }
#pragma unroll
            for (int mt = 0; mt < 2; mt++)
#pragma unroll
                for (int nt = 0; nt < 8; nt++)
                    mma_f16(c[mt][nt], af[mt], bf[nt]);
        }
        __syncthreads();
    }

    int rows_valid = n_e - row0;
    int gq = lane >> 2, tg = lane & 3;
#pragma unroll
    for (int mt = 0; mt < 2; mt++)
#pragma unroll
        for (int nt = 0; nt < 8; nt++) {
            int col = nb + wn + nt * 8 + tg * 2;
#pragma unroll
            for (int half = 0; half < 2; half++) {
                int r = wm + mt * 16 + gq + half * 8;
                if (r < rows_valid) {
                    float gw = s_w[r];
                    float* orow = out + (size_t)s_tok[r] * DDIM + col;
                    atomicAdd(orow,     c[mt][nt][half * 2]     * gw);
                    atomicAdd(orow + 1, c[mt][nt][half * 2 + 1] * gw);
                }
            }
        }
}

// ---------------- launch ----------------
extern "C" void kernel_launch(void* const* d_in, const int* in_sizes, int n_in,
                              void* d_out, int out_size) {
    (void)in_sizes; (void)n_in; (void)out_size;
    const float* x  = (const float*)d_in[0];
    const float* rw = (const float*)d_in[1];
    const float* w1 = (const float*)d_in[2];
    const float* w2 = (const float*)d_in[3];
    float* out = (float*)d_out;

    cudaFuncSetAttribute(fc1_kernel, cudaFuncAttributeMaxDynamicSharedMemorySize, SMEM_TOTAL);
    cudaFuncSetAttribute(fc2_kernel, cudaFuncAttributeMaxDynamicSharedMemorySize, SMEM_TOTAL);

    init_kernel<<<(T_TOK * DDIM + 255) / 256, 256>>>(out);

    __half *xh, *w1h, *w2h;
    cudaGetSymbolAddress((void**)&xh, g_xh);
    cudaGetSymbolAddress((void**)&w1h, g_w1h);
    cudaGetSymbolAddress((void**)&w2h, g_w2h);
    tohalf_kernel<<<(T_TOK * DDIM / 4) / 256, 256>>>(x, xh);
    tohalf_kernel<<<(int)(((size_t)NEXP * DDIM * HDIM / 4) / 256), 256>>>(w1, w1h);
    tohalf_kernel<<<(int)(((size_t)NEXP * HDIM * DDIM / 4) / 256), 256>>>(w2, w2h);

    router_kernel<<<T_TOK / 8, 256>>>(x, rw);
    offsets_kernel<<<1, 32>>>();

    dim3 g1(NEXP * NBM, HDIM / BN);   // 256 x 32
    fc1_kernel<<<g1, 256, SMEM_TOTAL>>>();
    dim3 g2(NEXP * NBM, DDIM / BN);   // 256 x 8
    fc2_kernel<<<g2, 256, SMEM_TOTAL>>>(out);
}